// round 1
// baseline (speedup 1.0000x reference)
#include <cuda_runtime.h>
#include <cuda_bf16.h>

#define D_IN   128
#define D_OUT  64
#define MAX_NODES 50048   // 50000 rounded up

// Scratch (no allocations allowed): h = x@W^T + b, and degree accumulator.
__device__ float g_h[(size_t)MAX_NODES * D_OUT];
__device__ float g_deg[MAX_NODES];

// ---------------------------------------------------------------------------
// Kernel 1: zero d_out (as float4) and g_deg
// ---------------------------------------------------------------------------
__global__ void zero_kernel(float4* __restrict__ out4, int n4, int n_nodes) {
    int i = blockIdx.x * blockDim.x + threadIdx.x;
    float4 z = make_float4(0.f, 0.f, 0.f, 0.f);
    if (i < n4) out4[i] = z;
    if (i < n_nodes) g_deg[i] = 0.f;
}

// ---------------------------------------------------------------------------
// Kernel 2: GEMM  h[N,64] = x[N,128] @ W[64,128]^T + b
// Block: 128 threads, computes 64 nodes x 64 outs.
// Smem tiles: x (64x128 f32) and W (64x128 f32), stored as float4 with pad.
// Thread (tx = tid%16, ty = tid/16) computes 8 nodes {ty+8i} x 4 outs {tx+16j}.
// ---------------------------------------------------------------------------
__global__ void __launch_bounds__(128) gemm_kernel(
    const float* __restrict__ x, const float* __restrict__ W,
    const float* __restrict__ b, int N)
{
    __shared__ float4 xs[64][33];   // pad to 33 float4 (=132 floats) per row
    __shared__ float4 ws[64][33];

    const int tid = threadIdx.x;
    const int nb  = blockIdx.x * 64;

    // Load W tile (64*32 float4, 16 per thread, coalesced)
    const float4* W4 = (const float4*)W;
#pragma unroll
    for (int i = 0; i < 16; i++) {
        int lin = tid + 128 * i;          // 0..2047
        int r = lin >> 5, c = lin & 31;
        ws[r][c] = W4[lin];
    }
    // Load x tile (guarded tail)
    const float4* x4 = (const float4*)x;
#pragma unroll
    for (int i = 0; i < 16; i++) {
        int lin = tid + 128 * i;
        int r = lin >> 5, c = lin & 31;
        int node = nb + r;
        float4 v = make_float4(0.f, 0.f, 0.f, 0.f);
        if (node < N) v = x4[node * 32 + c];
        xs[r][c] = v;
    }
    __syncthreads();

    const int tx = tid & 15;
    const int ty = tid >> 4;

    float acc[8][4];
#pragma unroll
    for (int i = 0; i < 8; i++)
#pragma unroll
        for (int j = 0; j < 4; j++) acc[i][j] = 0.f;

#pragma unroll 4
    for (int k = 0; k < 32; k++) {
        float4 xv[8], wv[4];
#pragma unroll
        for (int i = 0; i < 8; i++) xv[i] = xs[ty + 8 * i][k];
#pragma unroll
        for (int j = 0; j < 4; j++) wv[j] = ws[tx + 16 * j][k];
#pragma unroll
        for (int i = 0; i < 8; i++) {
#pragma unroll
            for (int j = 0; j < 4; j++) {
                acc[i][j] += xv[i].x * wv[j].x;
                acc[i][j] += xv[i].y * wv[j].y;
                acc[i][j] += xv[i].z * wv[j].z;
                acc[i][j] += xv[i].w * wv[j].w;
            }
        }
    }

    float bias[4];
#pragma unroll
    for (int j = 0; j < 4; j++) bias[j] = __ldg(&b[tx + 16 * j]);

#pragma unroll
    for (int i = 0; i < 8; i++) {
        int node = nb + ty + 8 * i;
        if (node < N) {
#pragma unroll
            for (int j = 0; j < 4; j++)
                g_h[(size_t)node * D_OUT + tx + 16 * j] = acc[i][j] + bias[j];
        }
    }
}

// ---------------------------------------------------------------------------
// Kernel 3: edge scatter.  16 threads per edge, one float4 (4 outs) each.
// out[row[e]] += h[col[e]]  via red.global.add.v4.f32 (L2 vector atomics),
// deg[row[e]] += 1 (one lane per edge).
// ---------------------------------------------------------------------------
__global__ void scatter_kernel(const int* __restrict__ row,
                               const int* __restrict__ col,
                               float* __restrict__ out, int E)
{
    int t = blockIdx.x * blockDim.x + threadIdx.x;
    int e = t >> 4;
    int lane = t & 15;
    if (e >= E) return;

    int r = __ldg(&row[e]);
    int c = __ldg(&col[e]);

    const float4* h4 = (const float4*)g_h;
    float4 v = h4[c * 16 + lane];

    float* dst = out + (size_t)r * D_OUT + lane * 4;
    asm volatile("red.global.add.v4.f32 [%0], {%1, %2, %3, %4};"
                 :: "l"(dst), "f"(v.x), "f"(v.y), "f"(v.z), "f"(v.w)
                 : "memory");

    if (lane == 0) atomicAdd(&g_deg[r], 1.0f);
}

// ---------------------------------------------------------------------------
// Kernel 4: normalize out[i] /= max(deg[i], 1)
// ---------------------------------------------------------------------------
__global__ void norm_kernel(float4* __restrict__ out4, int N)
{
    int i = blockIdx.x * blockDim.x + threadIdx.x;  // over N*16 float4
    if (i >= N * 16) return;
    int node = i >> 4;
    float d = g_deg[node];
    float s = 1.0f / fmaxf(d, 1.0f);
    float4 v = out4[i];
    v.x *= s; v.y *= s; v.z *= s; v.w *= s;
    out4[i] = v;
}

// ---------------------------------------------------------------------------
extern "C" void kernel_launch(void* const* d_in, const int* in_sizes, int n_in,
                              void* d_out, int out_size)
{
    const float* x   = (const float*)d_in[0];
    const float* W   = (const float*)d_in[1];
    const float* b   = (const float*)d_in[2];
    const int*   row = (const int*)d_in[3];
    const int*   col = (const int*)d_in[4];
    float* out = (float*)d_out;

    int N = in_sizes[0] / D_IN;   // 50000
    int E = in_sizes[3];          // 800000

    int n4 = N * (D_OUT / 4);     // N*16 float4 in out

    {   // zero out + deg
        int threads = 256;
        int blocks = (n4 + threads - 1) / threads;
        zero_kernel<<<blocks, threads>>>((float4*)out, n4, N);
    }
    {   // h = x @ W^T + b
        int blocks = (N + 63) / 64;
        gemm_kernel<<<blocks, 128>>>(x, W, b, N);
    }
    {   // scatter-add
        long long total = (long long)E * 16;
        int threads = 256;
        int blocks = (int)((total + threads - 1) / threads);
        scatter_kernel<<<blocks, threads>>>(row, col, out, E);
    }
    {   // normalize
        int threads = 256;
        int blocks = (N * 16 + threads - 1) / threads;
        norm_kernel<<<blocks, 256>>>((float4*)out, N);
    }
}

// round 2
// speedup vs baseline: 1.0647x; 1.0647x over previous
#include <cuda_runtime.h>
#include <cuda_bf16.h>

#define D_IN   128
#define D_OUT  64
#define MAX_NODES 50048
#define MAX_EDGES 1048576
#define CHUNK 512

// Scratch (device globals; no allocations allowed)
__device__ float g_h[(size_t)MAX_NODES * D_OUT];   // projected features
__device__ int   g_cnt[MAX_NODES];                  // in-degree histogram
__device__ int   g_row_ptr[MAX_NODES];              // exclusive scan of cnt
__device__ int   g_fill_ptr[MAX_NODES];             // fill cursors (copy of row_ptr)
__device__ int   g_adj[MAX_EDGES];                  // col indices grouped by row
__device__ int   g_chunk_base[CHUNK];               // scan partials

// ---------------------------------------------------------------------------
// K0: zero histogram counters
// ---------------------------------------------------------------------------
__global__ void zero_cnt_kernel(int n) {
    int i = blockIdx.x * blockDim.x + threadIdx.x;
    if (i < n) g_cnt[i] = 0;
}

// ---------------------------------------------------------------------------
// K1: histogram of row[] (in-degree)
// ---------------------------------------------------------------------------
__global__ void hist_kernel(const int* __restrict__ row, int E) {
    int e = blockIdx.x * blockDim.x + threadIdx.x;
    if (e < E) atomicAdd(&g_cnt[__ldg(&row[e])], 1);
}

// ---------------------------------------------------------------------------
// K2a: per-chunk sums of g_cnt (chunks of CHUNK)
// ---------------------------------------------------------------------------
__global__ void __launch_bounds__(CHUNK) chunk_sum_kernel(int n) {
    __shared__ int s[CHUNK];
    int tid = threadIdx.x;
    int gid = blockIdx.x * CHUNK + tid;
    s[tid] = (gid < n) ? g_cnt[gid] : 0;
    __syncthreads();
#pragma unroll
    for (int off = CHUNK / 2; off > 0; off >>= 1) {
        if (tid < off) s[tid] += s[tid + off];
        __syncthreads();
    }
    if (tid == 0) g_chunk_base[blockIdx.x] = s[0];   // raw sum for now
}

// ---------------------------------------------------------------------------
// K2b: exclusive scan of chunk sums (single block, nchunks <= CHUNK)
// ---------------------------------------------------------------------------
__global__ void __launch_bounds__(CHUNK) scan_partials_kernel(int nchunks) {
    __shared__ int s[CHUNK];
    int tid = threadIdx.x;
    int v = (tid < nchunks) ? g_chunk_base[tid] : 0;
    s[tid] = v;
    __syncthreads();
#pragma unroll
    for (int off = 1; off < CHUNK; off <<= 1) {
        int t = (tid >= off) ? s[tid - off] : 0;
        __syncthreads();
        s[tid] += t;
        __syncthreads();
    }
    if (tid < nchunks) g_chunk_base[tid] = s[tid] - v;   // exclusive
}

// ---------------------------------------------------------------------------
// K2c: per-chunk exclusive scan + base -> row_ptr, fill_ptr
// ---------------------------------------------------------------------------
__global__ void __launch_bounds__(CHUNK) scan_chunk_kernel(int n) {
    __shared__ int s[CHUNK];
    int tid = threadIdx.x;
    int gid = blockIdx.x * CHUNK + tid;
    int v = (gid < n) ? g_cnt[gid] : 0;
    s[tid] = v;
    __syncthreads();
#pragma unroll
    for (int off = 1; off < CHUNK; off <<= 1) {
        int t = (tid >= off) ? s[tid - off] : 0;
        __syncthreads();
        s[tid] += t;
        __syncthreads();
    }
    if (gid < n) {
        int excl = g_chunk_base[blockIdx.x] + s[tid] - v;
        g_row_ptr[gid]  = excl;
        g_fill_ptr[gid] = excl;
    }
}

// ---------------------------------------------------------------------------
// K3: fill adjacency: for each edge, place col into its row's bucket
// ---------------------------------------------------------------------------
__global__ void fill_kernel(const int* __restrict__ row,
                            const int* __restrict__ col, int E) {
    int e = blockIdx.x * blockDim.x + threadIdx.x;
    if (e >= E) return;
    int r = __ldg(&row[e]);
    int pos = atomicAdd(&g_fill_ptr[r], 1);
    g_adj[pos] = __ldg(&col[e]);
}

// ---------------------------------------------------------------------------
// K4: GEMM  h[N,64] = x[N,128] @ W[64,128]^T + b   (unchanged from R1)
// ---------------------------------------------------------------------------
__global__ void __launch_bounds__(128) gemm_kernel(
    const float* __restrict__ x, const float* __restrict__ W,
    const float* __restrict__ b, int N)
{
    __shared__ float4 xs[64][33];
    __shared__ float4 ws[64][33];

    const int tid = threadIdx.x;
    const int nb  = blockIdx.x * 64;

    const float4* W4 = (const float4*)W;
#pragma unroll
    for (int i = 0; i < 16; i++) {
        int lin = tid + 128 * i;
        int r = lin >> 5, c = lin & 31;
        ws[r][c] = W4[lin];
    }
    const float4* x4 = (const float4*)x;
#pragma unroll
    for (int i = 0; i < 16; i++) {
        int lin = tid + 128 * i;
        int r = lin >> 5, c = lin & 31;
        int node = nb + r;
        float4 v = make_float4(0.f, 0.f, 0.f, 0.f);
        if (node < N) v = x4[node * 32 + c];
        xs[r][c] = v;
    }
    __syncthreads();

    const int tx = tid & 15;
    const int ty = tid >> 4;

    float acc[8][4];
#pragma unroll
    for (int i = 0; i < 8; i++)
#pragma unroll
        for (int j = 0; j < 4; j++) acc[i][j] = 0.f;

#pragma unroll 4
    for (int k = 0; k < 32; k++) {
        float4 xv[8], wv[4];
#pragma unroll
        for (int i = 0; i < 8; i++) xv[i] = xs[ty + 8 * i][k];
#pragma unroll
        for (int j = 0; j < 4; j++) wv[j] = ws[tx + 16 * j][k];
#pragma unroll
        for (int i = 0; i < 8; i++) {
#pragma unroll
            for (int j = 0; j < 4; j++) {
                acc[i][j] += xv[i].x * wv[j].x;
                acc[i][j] += xv[i].y * wv[j].y;
                acc[i][j] += xv[i].z * wv[j].z;
                acc[i][j] += xv[i].w * wv[j].w;
            }
        }
    }

    float bias[4];
#pragma unroll
    for (int j = 0; j < 4; j++) bias[j] = __ldg(&b[tx + 16 * j]);

#pragma unroll
    for (int i = 0; i < 8; i++) {
        int node = nb + ty + 8 * i;
        if (node < N) {
#pragma unroll
            for (int j = 0; j < 4; j++)
                g_h[(size_t)node * D_OUT + tx + 16 * j] = acc[i][j] + bias[j];
        }
    }
}

// ---------------------------------------------------------------------------
// K5: aggregate + normalize + write out.
// 16 lanes per node; each lane owns one float4 (4 of the 64 output dims).
// acc = sum over node's edges of h[col]; out = acc / max(deg,1).
// No atomics; out needs no pre-zero (deg==0 writes zeros).
// ---------------------------------------------------------------------------
__global__ void __launch_bounds__(256) aggregate_kernel(float* __restrict__ out, int N)
{
    int t = blockIdx.x * blockDim.x + threadIdx.x;
    int node = t >> 4;
    int lane = t & 15;
    if (node >= N) return;

    int start = __ldg(&g_row_ptr[node]);
    int deg   = __ldg(&g_cnt[node]);

    const float4* h4 = (const float4*)g_h;
    float4 acc = make_float4(0.f, 0.f, 0.f, 0.f);

    int j = 0;
    for (; j + 4 <= deg; j += 4) {
        int c0 = __ldg(&g_adj[start + j]);
        int c1 = __ldg(&g_adj[start + j + 1]);
        int c2 = __ldg(&g_adj[start + j + 2]);
        int c3 = __ldg(&g_adj[start + j + 3]);
        float4 a0 = h4[c0 * 16 + lane];
        float4 a1 = h4[c1 * 16 + lane];
        float4 a2 = h4[c2 * 16 + lane];
        float4 a3 = h4[c3 * 16 + lane];
        acc.x += a0.x + a1.x + a2.x + a3.x;
        acc.y += a0.y + a1.y + a2.y + a3.y;
        acc.z += a0.z + a1.z + a2.z + a3.z;
        acc.w += a0.w + a1.w + a2.w + a3.w;
    }
    for (; j < deg; j++) {
        int c = __ldg(&g_adj[start + j]);
        float4 a = h4[c * 16 + lane];
        acc.x += a.x; acc.y += a.y; acc.z += a.z; acc.w += a.w;
    }

    float s = 1.0f / fmaxf((float)deg, 1.0f);
    acc.x *= s; acc.y *= s; acc.z *= s; acc.w *= s;
    ((float4*)out)[node * 16 + lane] = acc;
}

// ---------------------------------------------------------------------------
extern "C" void kernel_launch(void* const* d_in, const int* in_sizes, int n_in,
                              void* d_out, int out_size)
{
    const float* x   = (const float*)d_in[0];
    const float* W   = (const float*)d_in[1];
    const float* b   = (const float*)d_in[2];
    const int*   row = (const int*)d_in[3];
    const int*   col = (const int*)d_in[4];
    float* out = (float*)d_out;

    int N = in_sizes[0] / D_IN;   // 50000
    int E = in_sizes[3];          // 800000

    int nchunks = (N + CHUNK - 1) / CHUNK;

    zero_cnt_kernel<<<(N + 255) / 256, 256>>>(N);
    hist_kernel<<<(E + 255) / 256, 256>>>(row, E);
    chunk_sum_kernel<<<nchunks, CHUNK>>>(N);
    scan_partials_kernel<<<1, CHUNK>>>(nchunks);
    scan_chunk_kernel<<<nchunks, CHUNK>>>(N);
    fill_kernel<<<(E + 255) / 256, 256>>>(row, col, E);
    gemm_kernel<<<(N + 63) / 64, 128>>>(x, W, b, N);

    long long total = (long long)N * 16;
    aggregate_kernel<<<(int)((total + 255) / 256), 256>>>(out, N);
}